// round 9
// baseline (speedup 1.0000x reference)
#include <cuda_runtime.h>
#include <math.h>

// ---------------------------------------------------------------------------
// Problem constants
// ---------------------------------------------------------------------------
#define N_NODES 50000
#define T_WIN   3
#define E_PER_T 100000
#define HID     128
#define NH      8
#define DK      16
#define M_ROWS  (T_WIN * N_NODES)          // 150000 rows
#define TN      (T_WIN * N_NODES)

// ---------------------------------------------------------------------------
// Device scratch
// ---------------------------------------------------------------------------
__device__ float g_q[(size_t)M_ROWS * HID];
__device__ float g_k[(size_t)M_ROWS * HID];
__device__ float g_v[(size_t)M_ROWS * HID];
__device__ float g_hc[(size_t)TN * HID];        // normalized causal + residual x
__device__ float g_hs[(size_t)TN * HID];        // normalized spurious
__device__ int   g_cnt[T_WIN * N_NODES];        // histogram, then CSR cursor
__device__ int   g_off[T_WIN * (N_NODES + 1)];  // CSR offsets
__device__ int   g_csr[T_WIN * E_PER_T];        // src node ids, grouped by target

// ---------------------------------------------------------------------------
// Packed fp32x2 helpers (B300 FFMA2 path)
// ---------------------------------------------------------------------------
typedef unsigned long long u64;

__device__ __forceinline__ u64 fma2(u64 a, u64 b, u64 c) {
    u64 d;
    asm("fma.rn.f32x2 %0, %1, %2, %3;" : "=l"(d) : "l"(a), "l"(b), "l"(c));
    return d;
}
__device__ __forceinline__ u64 pack2(float lo, float hi) {
    u64 r;
    asm("mov.b64 %0, {%1, %2};" : "=l"(r) : "f"(lo), "f"(hi));
    return r;
}
__device__ __forceinline__ float2 unpack2(u64 v) {
    float2 f;
    asm("mov.b64 {%0, %1}, %2;" : "=f"(f.x), "=f"(f.y) : "l"(v));
    return f;
}

// cp.async 16B
__device__ __forceinline__ void cp16(void* sdst, const void* gsrc) {
    unsigned sa = (unsigned)__cvta_generic_to_shared(sdst);
    asm volatile("cp.async.ca.shared.global [%0], [%1], 16;\n"
                 :: "r"(sa), "l"(gsrc) : "memory");
}
__device__ __forceinline__ void cp_commit() {
    asm volatile("cp.async.commit_group;\n" ::: "memory");
}

// ---------------------------------------------------------------------------
// CSR build: zero -> count -> scan -> fill
// ---------------------------------------------------------------------------
__global__ void zero_cnt_kernel() {
    int i = blockIdx.x * blockDim.x + threadIdx.x;
    if (i < T_WIN * N_NODES) g_cnt[i] = 0;
}

__global__ void count_kernel(const int* __restrict__ ei) {
    int g = blockIdx.x * blockDim.x + threadIdx.x;
    if (g >= T_WIN * E_PER_T) return;
    int t   = g / E_PER_T;
    int idx = g - t * E_PER_T;
    int tar = ei[(size_t)t * 2 * E_PER_T + E_PER_T + idx];
    atomicAdd(&g_cnt[t * N_NODES + tar], 1);
}

// One block (1024 thr) per t: exclusive scan of 50000 counts.
__global__ void __launch_bounds__(1024) scan_kernel() {
    const int t    = blockIdx.x;
    const int tid  = threadIdx.x;
    const int lane = tid & 31;
    const int wid  = tid >> 5;
    __shared__ int wsum[32];
    __shared__ int sbase;
    if (tid == 0) sbase = 0;
    __syncthreads();

    for (int c0 = 0; c0 < N_NODES; c0 += 1024) {
        int i = c0 + tid;
        int v = (i < N_NODES) ? g_cnt[t * N_NODES + i] : 0;
        int incl = v;
        #pragma unroll
        for (int o = 1; o < 32; o <<= 1) {
            int u = __shfl_up_sync(0xFFFFFFFFu, incl, o);
            if (lane >= o) incl += u;
        }
        if (lane == 31) wsum[wid] = incl;
        __syncthreads();
        if (wid == 0) {
            int wv = wsum[lane];
            #pragma unroll
            for (int o = 1; o < 32; o <<= 1) {
                int u = __shfl_up_sync(0xFFFFFFFFu, wv, o);
                if (lane >= o) wv += u;
            }
            wsum[lane] = wv;
        }
        __syncthreads();
        int excl = (wid > 0 ? wsum[wid - 1] : 0) + sbase + incl - v;
        if (i < N_NODES) {
            g_off[t * (N_NODES + 1) + i] = excl;
            g_cnt[t * N_NODES + i]       = excl;   // becomes fill cursor
        }
        __syncthreads();
        if (tid == 0) sbase += wsum[31];
        __syncthreads();
    }
    if (tid == 0) g_off[t * (N_NODES + 1) + N_NODES] = sbase;
}

__global__ void fill_kernel(const int* __restrict__ ei) {
    int g = blockIdx.x * blockDim.x + threadIdx.x;
    if (g >= T_WIN * E_PER_T) return;
    int t   = g / E_PER_T;
    int idx = g - t * E_PER_T;
    int src = ei[(size_t)t * 2 * E_PER_T + idx];
    int tar = ei[(size_t)t * 2 * E_PER_T + E_PER_T + idx];
    int pos = atomicAdd(&g_cnt[t * N_NODES + tar], 1);
    g_csr[(size_t)t * E_PER_T + pos] = src;
}

// ---------------------------------------------------------------------------
// K_qkv: [150000 x 128] @ [128 x 128] + b, packed f32x2 math
// ---------------------------------------------------------------------------
__global__ void __launch_bounds__(256) qkv_kernel(
        const float* __restrict__ x,
        const float* __restrict__ Wq, const float* __restrict__ bq,
        const float* __restrict__ Wk, const float* __restrict__ bk,
        const float* __restrict__ Wv, const float* __restrict__ bv) {
    const float* W; const float* b; float* out;
    if (blockIdx.y == 0)      { W = Wq; b = bq; out = g_q; }
    else if (blockIdx.y == 1) { W = Wk; b = bk; out = g_k; }
    else                      { W = Wv; b = bv; out = g_v; }

    __shared__ float Xs[64][33];
    __shared__ float Ws[32][128];

    const int tid  = threadIdx.x;
    const int m0   = blockIdx.x * 64;
    const int ty   = tid >> 4;
    const int tx   = tid & 15;
    const int row0 = ty * 4;
    const int col0 = tx * 8;

    u64 acc[4][4];
    #pragma unroll
    for (int i = 0; i < 4; i++)
        #pragma unroll
        for (int j = 0; j < 4; j++) acc[i][j] = 0ull;

    for (int kc = 0; kc < 128; kc += 32) {
        #pragma unroll
        for (int l = 0; l < 2; l++) {
            int f4 = tid + l * 256;
            int r  = f4 >> 3;
            int c4 = f4 & 7;
            int grow = m0 + r;
            float4 val = make_float4(0.f, 0.f, 0.f, 0.f);
            if (grow < M_ROWS)
                val = *(const float4*)&x[(size_t)grow * HID + kc + c4 * 4];
            Xs[r][c4 * 4 + 0] = val.x;
            Xs[r][c4 * 4 + 1] = val.y;
            Xs[r][c4 * 4 + 2] = val.z;
            Xs[r][c4 * 4 + 3] = val.w;
        }
        #pragma unroll
        for (int l = 0; l < 4; l++) {
            int f4 = tid + l * 256;
            int r  = f4 >> 5;
            int c4 = f4 & 31;
            *(float4*)&Ws[r][c4 * 4] =
                *(const float4*)&W[(size_t)(kc + r) * HID + c4 * 4];
        }
        __syncthreads();

        #pragma unroll
        for (int k = 0; k < 32; k++) {
            ulonglong2 wb0 = *(const ulonglong2*)&Ws[k][col0];
            ulonglong2 wb1 = *(const ulonglong2*)&Ws[k][col0 + 4];
            #pragma unroll
            for (int i = 0; i < 4; i++) {
                u64 ap = pack2(Xs[row0 + i][k], Xs[row0 + i][k]);
                acc[i][0] = fma2(ap, wb0.x, acc[i][0]);
                acc[i][1] = fma2(ap, wb0.y, acc[i][1]);
                acc[i][2] = fma2(ap, wb1.x, acc[i][2]);
                acc[i][3] = fma2(ap, wb1.y, acc[i][3]);
            }
        }
        __syncthreads();
    }

    #pragma unroll
    for (int i = 0; i < 4; i++) {
        int grow = m0 + row0 + i;
        if (grow < M_ROWS) {
            float o[8];
            #pragma unroll
            for (int j = 0; j < 4; j++) {
                float2 v = unpack2(acc[i][j]);
                o[j * 2]     = v.x + b[col0 + j * 2];
                o[j * 2 + 1] = v.y + b[col0 + j * 2 + 1];
            }
            *(float4*)&out[(size_t)grow * HID + col0]     = make_float4(o[0], o[1], o[2], o[3]);
            *(float4*)&out[(size_t)grow * HID + col0 + 4] = make_float4(o[4], o[5], o[6], o[7]);
        }
    }
}

// ---------------------------------------------------------------------------
// K_agg: warp per (t_tar, node). CSR gather; attention + dual softmax
// aggregation in registers.
// ---------------------------------------------------------------------------
__global__ void __launch_bounds__(256) agg_kernel(const float* __restrict__ x) {
    const int warp = (blockIdx.x * blockDim.x + threadIdx.x) >> 5;
    const int lane = threadIdx.x & 31;
    const int t_tar = blockIdx.y;
    if (warp >= N_NODES) return;
    const int n = warp;

    const size_t rowoff = ((size_t)t_tar * N_NODES + n) * HID + lane * 4;
    const float4 q4 = *(const float4*)&g_q[rowoff];

    float ac0 = 0.f, ac1 = 0.f, ac2 = 0.f, ac3 = 0.f;
    float as0 = 0.f, as1 = 0.f, as2 = 0.f, as3 = 0.f;
    float sc = 0.f, ss = 0.f;

    for (int ts = 0; ts <= t_tar; ts++) {
        const int s0 = g_off[ts * (N_NODES + 1) + n];
        const int s1 = g_off[ts * (N_NODES + 1) + n + 1];
        const int* csr = g_csr + (size_t)ts * E_PER_T;
        const float* kb = g_k + (size_t)ts * N_NODES * HID;
        const float* vb = g_v + (size_t)ts * N_NODES * HID;

        for (int e = s0; e < s1; e++) {
            int src = csr[e];
            size_t so = (size_t)src * HID + lane * 4;
            float4 k4 = *(const float4*)&kb[so];
            float4 v4 = *(const float4*)&vb[so];

            float d = q4.x * k4.x + q4.y * k4.y + q4.z * k4.z + q4.w * k4.w;
            d += __shfl_xor_sync(0xFFFFFFFFu, d, 1);
            d += __shfl_xor_sync(0xFFFFFFFFu, d, 2);
            float a  = d * 0.25f;          // 1/sqrt(16)
            float ec = expf(a);
            float es = expf(-a);
            sc += ec;  ss += es;
            ac0 = fmaf(ec, v4.x, ac0); ac1 = fmaf(ec, v4.y, ac1);
            ac2 = fmaf(ec, v4.z, ac2); ac3 = fmaf(ec, v4.w, ac3);
            as0 = fmaf(es, v4.x, as0); as1 = fmaf(es, v4.y, as1);
            as2 = fmaf(es, v4.z, as2); as3 = fmaf(es, v4.w, as3);
        }
    }

    const float ic = 1.0f / (sc + 1e-16f);
    const float is = 1.0f / (ss + 1e-16f);
    const float4 xv = *(const float4*)&x[rowoff];

    *(float4*)&g_hc[rowoff] = make_float4(fmaf(ac0, ic, xv.x), fmaf(ac1, ic, xv.y),
                                          fmaf(ac2, ic, xv.z), fmaf(ac3, ic, xv.w));
    *(float4*)&g_hs[rowoff] = make_float4(as0 * is, as1 * is, as2 * is, as3 * is);
}

// ---------------------------------------------------------------------------
// K_ffn v8:
//  GEMM1: hn as DUP u64 pairs; W1 cp.async double-buffered.
//    Per 2 k-rows: 4 W LDS.128 + 8 hn LDS.128 + 32 fma2.
//  GEMM2: partial-sum pairs (j, j+128); W2 pre-paired into split 16B-stride
//    arrays (conflict-free); staging is REGISTER-PREFETCH double-buffered
//    (16-jj chunks, 2x16KB in wbuf): LDG next chunk -> compute current ->
//    sync -> pack+STS -> sync. LDG latency hidden behind ~1000 cyc compute.
// ---------------------------------------------------------------------------
__device__ __forceinline__ float gelu_exact(float v) {
    return 0.5f * v * (1.0f + erff(v * 0.70710678118654752f));
}

// LayerNorm, write DUPLICATED u64 pairs
__device__ __forceinline__ void ln_store_dup(float4 h4, int lane,
                                             float4 lns, float4 lnb,
                                             u64* __restrict__ dst) {
    float s1 = h4.x + h4.y + h4.z + h4.w;
    float s2 = h4.x*h4.x + h4.y*h4.y + h4.z*h4.z + h4.w*h4.w;
    #pragma unroll
    for (int o = 16; o > 0; o >>= 1) {
        s1 += __shfl_xor_sync(0xFFFFFFFFu, s1, o);
        s2 += __shfl_xor_sync(0xFFFFFFFFu, s2, o);
    }
    float mu   = s1 * (1.0f / 128.0f);
    float var  = s2 * (1.0f / 128.0f) - mu * mu;
    float rstd = rsqrtf(var + 1e-5f);

    float h0 = (h4.x - mu) * rstd * lns.x + lnb.x;
    float h1 = (h4.y - mu) * rstd * lns.y + lnb.y;
    float h2 = (h4.z - mu) * rstd * lns.z + lnb.z;
    float h3 = (h4.w - mu) * rstd * lns.w + lnb.w;

    ulonglong2 p01, p23;
    p01.x = pack2(h0, h0); p01.y = pack2(h1, h1);
    p23.x = pack2(h2, h2); p23.y = pack2(h3, h3);
    *(ulonglong2*)&dst[lane * 4]     = p01;
    *(ulonglong2*)&dst[lane * 4 + 2] = p23;
}

__global__ void __launch_bounds__(256, 2) ffn_kernel(
        const float* __restrict__ ln_s, const float* __restrict__ ln_b,
        const float* __restrict__ W1, const float* __restrict__ b1,
        const float* __restrict__ W2, const float* __restrict__ b2,
        float* __restrict__ out) {
    __shared__ __align__(16) u64 sbuf[8][1024];   // 64 KB: hnd then gpair
    __shared__ __align__(16) u64 wbuf[4096];      // 32 KB: W1 db / W2 paired db

    const int tid  = threadIdx.x;
    const int wib  = tid >> 5;
    const int lane = tid & 31;
    const int wg   = blockIdx.x * 8 + wib;            // warp id over TN/4
    const bool active = (wg < TN / 4);

    u64* hnd   = sbuf[wib];                           // [8f][128] dup pairs
    u64* gpair = sbuf[wib];                           // [8f][128] (lo,hi) pairs
    float (*ws)[4096] = (float (*)[4096])wbuf;        // W1 staging view

    const float4 lns = active ? *(const float4*)&ln_s[lane * 4] : make_float4(0,0,0,0);
    const float4 lnb = active ? *(const float4*)&ln_b[lane * 4] : make_float4(0,0,0,0);

    // ---- kick off stage of W1 chunk 0 (16 rows x 256 = 16 KB)
    {
        const float4* g4 = (const float4*)W1;
        #pragma unroll
        for (int t = 0; t < 4; t++)
            cp16(&ws[0][(tid + t * 256) * 4], &g4[tid + t * 256]);
        cp_commit();
    }

    // ---- phase 0: LayerNorm for 8 instances (f = nn*2 + {c,s}), dup pairs
    if (active) {
        #pragma unroll
        for (int nn = 0; nn < 4; nn++) {
            size_t off = ((size_t)wg * 4 + nn) * HID + lane * 4;
            float4 c4 = *(const float4*)&g_hc[off];
            float4 s4 = *(const float4*)&g_hs[off];
            ln_store_dup(c4, lane, lns, lnb, &hnd[(nn * 2 + 0) * 128]);
            ln_store_dup(s4, lane, lns, lnb, &hnd[(nn * 2 + 1) * 128]);
        }
    }
    __syncwarp();

    // ---- GEMM1: lane owns j in {lane*4..+4} and {128+lane*4..+4}
    u64 a1[8][4];
    {
        ulonglong2 bA = *(const ulonglong2*)&b1[lane * 4];
        ulonglong2 bB = *(const ulonglong2*)&b1[128 + lane * 4];
        #pragma unroll
        for (int f = 0; f < 8; f++) {
            a1[f][0] = bA.x; a1[f][1] = bA.y; a1[f][2] = bB.x; a1[f][3] = bB.y;
        }
    }
    #pragma unroll 1
    for (int c = 0; c < 8; c++) {
        if (c < 7) {
            const float4* g4 = (const float4*)(W1 + (size_t)(c + 1) * 16 * 256);
            #pragma unroll
            for (int t = 0; t < 4; t++)
                cp16(&ws[(c + 1) & 1][(tid + t * 256) * 4], &g4[tid + t * 256]);
            cp_commit();
            asm volatile("cp.async.wait_group 1;\n" ::: "memory");
        } else {
            asm volatile("cp.async.wait_group 0;\n" ::: "memory");
        }
        __syncthreads();

        const float* wsb = ws[c & 1];
        #pragma unroll 1
        for (int ii = 0; ii < 16; ii += 2) {
            ulonglong2 wA0 = *(const ulonglong2*)&wsb[ii * 256 + lane * 4];
            ulonglong2 wB0 = *(const ulonglong2*)&wsb[ii * 256 + 128 + lane * 4];
            ulonglong2 wA1 = *(const ulonglong2*)&wsb[(ii + 1) * 256 + lane * 4];
            ulonglong2 wB1 = *(const ulonglong2*)&wsb[(ii + 1) * 256 + 128 + lane * 4];
            const int i = c * 16 + ii;

            #pragma unroll
            for (int f = 0; f < 8; f++) {
                ulonglong2 hp = *(const ulonglong2*)&hnd[f * 128 + i];  // dup(i), dup(i+1)
                a1[f][0] = fma2(hp.x, wA0.x, a1[f][0]);
                a1[f][1] = fma2(hp.x, wA0.y, a1[f][1]);
                a1[f][2] = fma2(hp.x, wB0.x, a1[f][2]);
                a1[f][3] = fma2(hp.x, wB0.y, a1[f][3]);
                a1[f][0] = fma2(hp.y, wA1.x, a1[f][0]);
                a1[f][1] = fma2(hp.y, wA1.y, a1[f][1]);
                a1[f][2] = fma2(hp.y, wB1.x, a1[f][2]);
                a1[f][3] = fma2(hp.y, wB1.y, a1[f][3]);
            }
        }
        __syncthreads();
    }

    // ---- GELU -> gpair[f][j] = (gelu(g[j]), gelu(g[j+128])), j = lane*4+r
    __syncwarp();
    #pragma unroll
    for (int f = 0; f < 8; f++) {
        float2 lo01 = unpack2(a1[f][0]);   // cols 4l, 4l+1
        float2 lo23 = unpack2(a1[f][1]);   // cols 4l+2, 4l+3
        float2 hi01 = unpack2(a1[f][2]);   // cols 128+4l, 128+4l+1
        float2 hi23 = unpack2(a1[f][3]);
        ulonglong2 p01, p23;
        p01.x = pack2(gelu_exact(lo01.x), gelu_exact(hi01.x));
        p01.y = pack2(gelu_exact(lo01.y), gelu_exact(hi01.y));
        p23.x = pack2(gelu_exact(lo23.x), gelu_exact(hi23.x));
        p23.y = pack2(gelu_exact(lo23.y), gelu_exact(hi23.y));
        *(ulonglong2*)&gpair[f * 128 + lane * 4]     = p01;
        *(ulonglong2*)&gpair[f * 128 + lane * 4 + 2] = p23;
    }

    // ---- GEMM2: partial-sum pairs over (j, j+128); W2 pre-paired, split
    //      arrays (16B lane stride), register-prefetch double-buffered.
    //      Chunk = 16 j-pairs = 16 KB paired; buffers at wbuf[0], wbuf[2048].
    u64 a2[8][4];
    {
        float4 b2v = *(const float4*)&b2[lane * 4];
        u64 i0 = pack2(b2v.x, 0.f), i1 = pack2(b2v.y, 0.f);
        u64 i2 = pack2(b2v.z, 0.f), i3 = pack2(b2v.w, 0.f);
        #pragma unroll
        for (int f = 0; f < 8; f++) {
            a2[f][0] = i0; a2[f][1] = i1; a2[f][2] = i2; a2[f][3] = i3;
        }
    }

    const int pjj = tid >> 5;            // prefetch jj row: 0..7 (wib)
    const int pd4 = tid & 31;            // prefetch d4 col: 0..31
    float4 plo[2], phi[2];

    // prefetch + store chunk 0  (jj = pjj and pjj+8)
    #pragma unroll
    for (int it = 0; it < 2; it++) {
        int jj = pjj + it * 8;
        plo[it] = *(const float4*)&W2[(size_t)jj * 128 + pd4 * 4];
        phi[it] = *(const float4*)&W2[(size_t)(jj + 128) * 128 + pd4 * 4];
    }
    __syncthreads();                     // wbuf free (GEMM1 done)
    #pragma unroll
    for (int it = 0; it < 2; it++) {
        int jj = pjj + it * 8;
        ulonglong2 q01, q23;
        q01.x = pack2(plo[it].x, phi[it].x); q01.y = pack2(plo[it].y, phi[it].y);
        q23.x = pack2(plo[it].z, phi[it].z); q23.y = pack2(plo[it].w, phi[it].w);
        *(ulonglong2*)&wbuf[jj * 64 + pd4 * 2]        = q01;  // ws2a buf0
        *(ulonglong2*)&wbuf[1024 + jj * 64 + pd4 * 2] = q23;  // ws2b buf0
    }
    __syncthreads();

    #pragma unroll 1
    for (int c = 0; c < 8; c++) {
        // issue next chunk's LDGs (latency hidden by compute below)
        if (c < 7) {
            #pragma unroll
            for (int it = 0; it < 2; it++) {
                int j = (c + 1) * 16 + pjj + it * 8;
                plo[it] = *(const float4*)&W2[(size_t)j * 128 + pd4 * 4];
                phi[it] = *(const float4*)&W2[(size_t)(j + 128) * 128 + pd4 * 4];
            }
        }

        const u64* ba = wbuf + (c & 1) * 2048;
        const u64* bb = ba + 1024;
        #pragma unroll 2
        for (int jj = 0; jj < 16; jj += 2) {
            ulonglong2 wa0 = *(const ulonglong2*)&ba[jj * 64 + lane * 2];
            ulonglong2 wb0 = *(const ulonglong2*)&bb[jj * 64 + lane * 2];
            ulonglong2 wa1 = *(const ulonglong2*)&ba[(jj + 1) * 64 + lane * 2];
            ulonglong2 wb1 = *(const ulonglong2*)&bb[(jj + 1) * 64 + lane * 2];
            const int j = c * 16 + jj;
            #pragma unroll
            for (int f = 0; f < 8; f++) {
                ulonglong2 gp = *(const ulonglong2*)&gpair[f * 128 + j]; // j, j+1
                a2[f][0] = fma2(gp.x, wa0.x, a2[f][0]);
                a2[f][1] = fma2(gp.x, wa0.y, a2[f][1]);
                a2[f][2] = fma2(gp.x, wb0.x, a2[f][2]);
                a2[f][3] = fma2(gp.x, wb0.y, a2[f][3]);
                a2[f][0] = fma2(gp.y, wa1.x, a2[f][0]);
                a2[f][1] = fma2(gp.y, wa1.y, a2[f][1]);
                a2[f][2] = fma2(gp.y, wb1.x, a2[f][2]);
                a2[f][3] = fma2(gp.y, wb1.y, a2[f][3]);
            }
        }

        if (c < 7) {
            __syncthreads();             // all warps done reading dst buffer
            u64* na = wbuf + ((c + 1) & 1) * 2048;
            u64* nb = na + 1024;
            #pragma unroll
            for (int it = 0; it < 2; it++) {
                int jj = pjj + it * 8;
                ulonglong2 q01, q23;
                q01.x = pack2(plo[it].x, phi[it].x); q01.y = pack2(plo[it].y, phi[it].y);
                q23.x = pack2(plo[it].z, phi[it].z); q23.y = pack2(plo[it].w, phi[it].w);
                *(ulonglong2*)&na[jj * 64 + pd4 * 2] = q01;
                *(ulonglong2*)&nb[jj * 64 + pd4 * 2] = q23;
            }
            __syncthreads();             // stores visible
        }
    }

    if (!active) return;

    // ---- epilogue: horizontal add of partial-sum pairs, residual, write
    const size_t S = (size_t)TN * HID;
    #pragma unroll
    for (int nn = 0; nn < 4; nn++) {
        size_t off = ((size_t)wg * 4 + nn) * HID + lane * 4;
        float4 c4 = *(const float4*)&g_hc[off];
        float4 s4 = *(const float4*)&g_hs[off];

        float oc[4], os[4];
        #pragma unroll
        for (int r = 0; r < 4; r++) {
            float2 cv = unpack2(a2[nn * 2][r]);
            float2 sv = unpack2(a2[nn * 2 + 1][r]);
            oc[r] = cv.x + cv.y;
            os[r] = sv.x + sv.y;
        }
        oc[0] += c4.x; oc[1] += c4.y; oc[2] += c4.z; oc[3] += c4.w;
        os[0] += s4.x; os[1] += s4.y; os[2] += s4.z; os[3] += s4.w;

        *(float4*)&out[off]         = make_float4(oc[0]+os[0], oc[1]+os[1],
                                                  oc[2]+os[2], oc[3]+os[3]);
        *(float4*)&out[S + off]     = make_float4(oc[0], oc[1], oc[2], oc[3]);
        *(float4*)&out[2*S + off]   = make_float4(os[0], os[1], os[2], os[3]);
    }
}

// ---------------------------------------------------------------------------
// Launch
// ---------------------------------------------------------------------------
extern "C" void kernel_launch(void* const* d_in, const int* in_sizes, int n_in,
                              void* d_out, int out_size) {
    const float* x    = (const float*)d_in[0];
    const int*   ei   = (const int*)  d_in[1];
    const float* Wq   = (const float*)d_in[2];
    const float* bq   = (const float*)d_in[3];
    const float* Wk   = (const float*)d_in[4];
    const float* bk   = (const float*)d_in[5];
    const float* Wv   = (const float*)d_in[6];
    const float* bv   = (const float*)d_in[7];
    const float* ln_s = (const float*)d_in[8];
    const float* ln_b = (const float*)d_in[9];
    const float* W1   = (const float*)d_in[10];
    const float* b1   = (const float*)d_in[11];
    const float* W2   = (const float*)d_in[12];
    const float* b2   = (const float*)d_in[13];
    float* out = (float*)d_out;

    // CSR build (depends only on edge_index)
    zero_cnt_kernel<<<(T_WIN * N_NODES + 255) / 256, 256>>>();
    count_kernel<<<(T_WIN * E_PER_T + 255) / 256, 256>>>(ei);
    scan_kernel<<<T_WIN, 1024>>>();
    fill_kernel<<<(T_WIN * E_PER_T + 255) / 256, 256>>>(ei);

    // QKV projections
    qkv_kernel<<<dim3((M_ROWS + 63) / 64, 3), 256>>>(x, Wq, bq, Wk, bk, Wv, bv);

    // Gather-aggregate
    agg_kernel<<<dim3((N_NODES * 32 + 255) / 256, T_WIN), 256>>>(x);

    // Dual FFN (8 warps x 4 nodes per block)
    ffn_kernel<<<(TN / 4 + 7) / 8, 256>>>(ln_s, ln_b, W1, b1, W2, b2, out);
}

// round 10
// speedup vs baseline: 1.0907x; 1.0907x over previous
#include <cuda_runtime.h>
#include <math.h>

// ---------------------------------------------------------------------------
// Problem constants
// ---------------------------------------------------------------------------
#define N_NODES 50000
#define T_WIN   3
#define E_PER_T 100000
#define HID     128
#define NH      8
#define DK      16
#define M_ROWS  (T_WIN * N_NODES)          // 150000 rows
#define TN      (T_WIN * N_NODES)

// ---------------------------------------------------------------------------
// Device scratch
// ---------------------------------------------------------------------------
__device__ float g_q[(size_t)M_ROWS * HID];
__device__ float g_k[(size_t)M_ROWS * HID];
__device__ float g_v[(size_t)M_ROWS * HID];
__device__ float g_hc[(size_t)TN * HID];        // normalized causal + residual x
__device__ float g_hs[(size_t)TN * HID];        // normalized spurious
__device__ int   g_cnt[T_WIN * N_NODES];        // histogram, then CSR cursor
__device__ int   g_off[T_WIN * (N_NODES + 1)];  // CSR offsets
__device__ int   g_csr[T_WIN * E_PER_T];        // src node ids, grouped by target

// ---------------------------------------------------------------------------
// Packed fp32x2 helpers (B300 FFMA2 path)
// ---------------------------------------------------------------------------
typedef unsigned long long u64;

__device__ __forceinline__ u64 fma2(u64 a, u64 b, u64 c) {
    u64 d;
    asm("fma.rn.f32x2 %0, %1, %2, %3;" : "=l"(d) : "l"(a), "l"(b), "l"(c));
    return d;
}
__device__ __forceinline__ u64 pack2(float lo, float hi) {
    u64 r;
    asm("mov.b64 %0, {%1, %2};" : "=l"(r) : "f"(lo), "f"(hi));
    return r;
}
__device__ __forceinline__ float2 unpack2(u64 v) {
    float2 f;
    asm("mov.b64 {%0, %1}, %2;" : "=f"(f.x), "=f"(f.y) : "l"(v));
    return f;
}

// cp.async 16B
__device__ __forceinline__ void cp16(void* sdst, const void* gsrc) {
    unsigned sa = (unsigned)__cvta_generic_to_shared(sdst);
    asm volatile("cp.async.ca.shared.global [%0], [%1], 16;\n"
                 :: "r"(sa), "l"(gsrc) : "memory");
}
__device__ __forceinline__ void cp_commit() {
    asm volatile("cp.async.commit_group;\n" ::: "memory");
}

// ---------------------------------------------------------------------------
// CSR build: zero -> count -> scan -> fill
// ---------------------------------------------------------------------------
__global__ void zero_cnt_kernel() {
    int i = blockIdx.x * blockDim.x + threadIdx.x;
    if (i < T_WIN * N_NODES) g_cnt[i] = 0;
}

__global__ void count_kernel(const int* __restrict__ ei) {
    int g = blockIdx.x * blockDim.x + threadIdx.x;
    if (g >= T_WIN * E_PER_T) return;
    int t   = g / E_PER_T;
    int idx = g - t * E_PER_T;
    int tar = ei[(size_t)t * 2 * E_PER_T + E_PER_T + idx];
    atomicAdd(&g_cnt[t * N_NODES + tar], 1);
}

// One block (1024 thr) per t: exclusive scan of 50000 counts.
__global__ void __launch_bounds__(1024) scan_kernel() {
    const int t    = blockIdx.x;
    const int tid  = threadIdx.x;
    const int lane = tid & 31;
    const int wid  = tid >> 5;
    __shared__ int wsum[32];
    __shared__ int sbase;
    if (tid == 0) sbase = 0;
    __syncthreads();

    for (int c0 = 0; c0 < N_NODES; c0 += 1024) {
        int i = c0 + tid;
        int v = (i < N_NODES) ? g_cnt[t * N_NODES + i] : 0;
        int incl = v;
        #pragma unroll
        for (int o = 1; o < 32; o <<= 1) {
            int u = __shfl_up_sync(0xFFFFFFFFu, incl, o);
            if (lane >= o) incl += u;
        }
        if (lane == 31) wsum[wid] = incl;
        __syncthreads();
        if (wid == 0) {
            int wv = wsum[lane];
            #pragma unroll
            for (int o = 1; o < 32; o <<= 1) {
                int u = __shfl_up_sync(0xFFFFFFFFu, wv, o);
                if (lane >= o) wv += u;
            }
            wsum[lane] = wv;
        }
        __syncthreads();
        int excl = (wid > 0 ? wsum[wid - 1] : 0) + sbase + incl - v;
        if (i < N_NODES) {
            g_off[t * (N_NODES + 1) + i] = excl;
            g_cnt[t * N_NODES + i]       = excl;   // becomes fill cursor
        }
        __syncthreads();
        if (tid == 0) sbase += wsum[31];
        __syncthreads();
    }
    if (tid == 0) g_off[t * (N_NODES + 1) + N_NODES] = sbase;
}

__global__ void fill_kernel(const int* __restrict__ ei) {
    int g = blockIdx.x * blockDim.x + threadIdx.x;
    if (g >= T_WIN * E_PER_T) return;
    int t   = g / E_PER_T;
    int idx = g - t * E_PER_T;
    int src = ei[(size_t)t * 2 * E_PER_T + idx];
    int tar = ei[(size_t)t * 2 * E_PER_T + E_PER_T + idx];
    int pos = atomicAdd(&g_cnt[t * N_NODES + tar], 1);
    g_csr[(size_t)t * E_PER_T + pos] = src;
}

// ---------------------------------------------------------------------------
// K_qkv: [150000 x 128] @ [128 x 128] + b, packed f32x2 math
// ---------------------------------------------------------------------------
__global__ void __launch_bounds__(256) qkv_kernel(
        const float* __restrict__ x,
        const float* __restrict__ Wq, const float* __restrict__ bq,
        const float* __restrict__ Wk, const float* __restrict__ bk,
        const float* __restrict__ Wv, const float* __restrict__ bv) {
    const float* W; const float* b; float* out;
    if (blockIdx.y == 0)      { W = Wq; b = bq; out = g_q; }
    else if (blockIdx.y == 1) { W = Wk; b = bk; out = g_k; }
    else                      { W = Wv; b = bv; out = g_v; }

    __shared__ float Xs[64][33];
    __shared__ float Ws[32][128];

    const int tid  = threadIdx.x;
    const int m0   = blockIdx.x * 64;
    const int ty   = tid >> 4;
    const int tx   = tid & 15;
    const int row0 = ty * 4;
    const int col0 = tx * 8;

    u64 acc[4][4];
    #pragma unroll
    for (int i = 0; i < 4; i++)
        #pragma unroll
        for (int j = 0; j < 4; j++) acc[i][j] = 0ull;

    for (int kc = 0; kc < 128; kc += 32) {
        #pragma unroll
        for (int l = 0; l < 2; l++) {
            int f4 = tid + l * 256;
            int r  = f4 >> 3;
            int c4 = f4 & 7;
            int grow = m0 + r;
            float4 val = make_float4(0.f, 0.f, 0.f, 0.f);
            if (grow < M_ROWS)
                val = *(const float4*)&x[(size_t)grow * HID + kc + c4 * 4];
            Xs[r][c4 * 4 + 0] = val.x;
            Xs[r][c4 * 4 + 1] = val.y;
            Xs[r][c4 * 4 + 2] = val.z;
            Xs[r][c4 * 4 + 3] = val.w;
        }
        #pragma unroll
        for (int l = 0; l < 4; l++) {
            int f4 = tid + l * 256;
            int r  = f4 >> 5;
            int c4 = f4 & 31;
            *(float4*)&Ws[r][c4 * 4] =
                *(const float4*)&W[(size_t)(kc + r) * HID + c4 * 4];
        }
        __syncthreads();

        #pragma unroll
        for (int k = 0; k < 32; k++) {
            ulonglong2 wb0 = *(const ulonglong2*)&Ws[k][col0];
            ulonglong2 wb1 = *(const ulonglong2*)&Ws[k][col0 + 4];
            #pragma unroll
            for (int i = 0; i < 4; i++) {
                u64 ap = pack2(Xs[row0 + i][k], Xs[row0 + i][k]);
                acc[i][0] = fma2(ap, wb0.x, acc[i][0]);
                acc[i][1] = fma2(ap, wb0.y, acc[i][1]);
                acc[i][2] = fma2(ap, wb1.x, acc[i][2]);
                acc[i][3] = fma2(ap, wb1.y, acc[i][3]);
            }
        }
        __syncthreads();
    }

    #pragma unroll
    for (int i = 0; i < 4; i++) {
        int grow = m0 + row0 + i;
        if (grow < M_ROWS) {
            float o[8];
            #pragma unroll
            for (int j = 0; j < 4; j++) {
                float2 v = unpack2(acc[i][j]);
                o[j * 2]     = v.x + b[col0 + j * 2];
                o[j * 2 + 1] = v.y + b[col0 + j * 2 + 1];
            }
            *(float4*)&out[(size_t)grow * HID + col0]     = make_float4(o[0], o[1], o[2], o[3]);
            *(float4*)&out[(size_t)grow * HID + col0 + 4] = make_float4(o[4], o[5], o[6], o[7]);
        }
    }
}

// ---------------------------------------------------------------------------
// K_agg v2: warp per (t_tar, node), CSR gather, 2-edge ILP pipeline.
// Two independent k/v load + dot + shuffle + exp chains per iteration hide
// the per-edge dependency latency (LDG->SHFL(26)x2->MUFU exp).
// ---------------------------------------------------------------------------
__global__ void __launch_bounds__(256) agg_kernel(const float* __restrict__ x) {
    const int warp = (blockIdx.x * blockDim.x + threadIdx.x) >> 5;
    const int lane = threadIdx.x & 31;
    const int t_tar = blockIdx.y;
    if (warp >= N_NODES) return;
    const int n = warp;

    const size_t rowoff = ((size_t)t_tar * N_NODES + n) * HID + lane * 4;
    const float4 q4 = *(const float4*)&g_q[rowoff];

    float ac0 = 0.f, ac1 = 0.f, ac2 = 0.f, ac3 = 0.f;
    float as0 = 0.f, as1 = 0.f, as2 = 0.f, as3 = 0.f;
    float sc = 0.f, ss = 0.f;

    for (int ts = 0; ts <= t_tar; ts++) {
        const int s0 = g_off[ts * (N_NODES + 1) + n];
        const int s1 = g_off[ts * (N_NODES + 1) + n + 1];
        const int* csr = g_csr + (size_t)ts * E_PER_T;
        const float* kb = g_k + (size_t)ts * N_NODES * HID;
        const float* vb = g_v + (size_t)ts * N_NODES * HID;

        int e = s0;
        for (; e + 1 < s1; e += 2) {
            int srcA = csr[e];
            int srcB = csr[e + 1];
            size_t soA = (size_t)srcA * HID + lane * 4;
            size_t soB = (size_t)srcB * HID + lane * 4;
            float4 kA = *(const float4*)&kb[soA];
            float4 kB = *(const float4*)&kb[soB];
            float4 vA = *(const float4*)&vb[soA];
            float4 vB = *(const float4*)&vb[soB];

            float dA = q4.x * kA.x + q4.y * kA.y + q4.z * kA.z + q4.w * kA.w;
            float dB = q4.x * kB.x + q4.y * kB.y + q4.z * kB.z + q4.w * kB.w;
            dA += __shfl_xor_sync(0xFFFFFFFFu, dA, 1);
            dB += __shfl_xor_sync(0xFFFFFFFFu, dB, 1);
            dA += __shfl_xor_sync(0xFFFFFFFFu, dA, 2);
            dB += __shfl_xor_sync(0xFFFFFFFFu, dB, 2);
            float aA = dA * 0.25f;
            float aB = dB * 0.25f;
            float ecA = expf(aA), ecB = expf(aB);
            float esA = expf(-aA), esB = expf(-aB);

            sc += ecA + ecB;
            ss += esA + esB;
            ac0 = fmaf(ecA, vA.x, ac0); ac0 = fmaf(ecB, vB.x, ac0);
            ac1 = fmaf(ecA, vA.y, ac1); ac1 = fmaf(ecB, vB.y, ac1);
            ac2 = fmaf(ecA, vA.z, ac2); ac2 = fmaf(ecB, vB.z, ac2);
            ac3 = fmaf(ecA, vA.w, ac3); ac3 = fmaf(ecB, vB.w, ac3);
            as0 = fmaf(esA, vA.x, as0); as0 = fmaf(esB, vB.x, as0);
            as1 = fmaf(esA, vA.y, as1); as1 = fmaf(esB, vB.y, as1);
            as2 = fmaf(esA, vA.z, as2); as2 = fmaf(esB, vB.z, as2);
            as3 = fmaf(esA, vA.w, as3); as3 = fmaf(esB, vB.w, as3);
        }
        if (e < s1) {
            int src = csr[e];
            size_t so = (size_t)src * HID + lane * 4;
            float4 k4 = *(const float4*)&kb[so];
            float4 v4 = *(const float4*)&vb[so];

            float d = q4.x * k4.x + q4.y * k4.y + q4.z * k4.z + q4.w * k4.w;
            d += __shfl_xor_sync(0xFFFFFFFFu, d, 1);
            d += __shfl_xor_sync(0xFFFFFFFFu, d, 2);
            float a  = d * 0.25f;
            float ec = expf(a);
            float es = expf(-a);
            sc += ec;  ss += es;
            ac0 = fmaf(ec, v4.x, ac0); ac1 = fmaf(ec, v4.y, ac1);
            ac2 = fmaf(ec, v4.z, ac2); ac3 = fmaf(ec, v4.w, ac3);
            as0 = fmaf(es, v4.x, as0); as1 = fmaf(es, v4.y, as1);
            as2 = fmaf(es, v4.z, as2); as3 = fmaf(es, v4.w, as3);
        }
    }

    const float ic = 1.0f / (sc + 1e-16f);
    const float is = 1.0f / (ss + 1e-16f);
    const float4 xv = *(const float4*)&x[rowoff];

    *(float4*)&g_hc[rowoff] = make_float4(fmaf(ac0, ic, xv.x), fmaf(ac1, ic, xv.y),
                                          fmaf(ac2, ic, xv.z), fmaf(ac3, ic, xv.w));
    *(float4*)&g_hs[rowoff] = make_float4(as0 * is, as1 * is, as2 * is, as3 * is);
}

// ---------------------------------------------------------------------------
// K_ffn (round-6 v5, the empirical best): warp = 4 nodes (8 instances),
// f32x2 packed math, 2 blocks/SM. W1/W2 staged block-cooperatively via
// cp.async double buffer. Lane owns j-cols {lane*4..+4, 128+lane*4..+4}.
// ---------------------------------------------------------------------------
__device__ __forceinline__ float gelu_exact(float v) {
    return 0.5f * v * (1.0f + erff(v * 0.70710678118654752f));
}

__device__ __forceinline__ void ln_store4(float4 h4, int lane,
                                          float4 lns, float4 lnb,
                                          float* __restrict__ dst) {
    float s1 = h4.x + h4.y + h4.z + h4.w;
    float s2 = h4.x*h4.x + h4.y*h4.y + h4.z*h4.z + h4.w*h4.w;
    #pragma unroll
    for (int o = 16; o > 0; o >>= 1) {
        s1 += __shfl_xor_sync(0xFFFFFFFFu, s1, o);
        s2 += __shfl_xor_sync(0xFFFFFFFFu, s2, o);
    }
    float mu   = s1 * (1.0f / 128.0f);
    float var  = s2 * (1.0f / 128.0f) - mu * mu;
    float rstd = rsqrtf(var + 1e-5f);

    *(float4*)&dst[lane * 4] = make_float4(
        (h4.x - mu) * rstd * lns.x + lnb.x,
        (h4.y - mu) * rstd * lns.y + lnb.y,
        (h4.z - mu) * rstd * lns.z + lnb.z,
        (h4.w - mu) * rstd * lns.w + lnb.w);
}

__global__ void __launch_bounds__(256, 2) ffn_kernel(
        const float* __restrict__ ln_s, const float* __restrict__ ln_b,
        const float* __restrict__ W1, const float* __restrict__ b1,
        const float* __restrict__ W2, const float* __restrict__ b2,
        float* __restrict__ out) {
    __shared__ float sbuf[8][2048];                    // 64 KB per-warp hn/g
    __shared__ __align__(16) float ws[2][4096];        // 32 KB W stage (db)

    const int tid  = threadIdx.x;
    const int wib  = tid >> 5;
    const int lane = tid & 31;
    const int wg   = blockIdx.x * 8 + wib;     // warp id over TN/4 = 37500
    const bool active = (wg < TN / 4);

    float* hnf = sbuf[wib];
    float* gb  = sbuf[wib];

    const float4 lns = active ? *(const float4*)&ln_s[lane * 4] : make_float4(0,0,0,0);
    const float4 lnb = active ? *(const float4*)&ln_b[lane * 4] : make_float4(0,0,0,0);

    // ---- kick off stage of W1 chunk 0 (16 rows x 256 = 16 KB)
    {
        const float4* g4 = (const float4*)W1;
        #pragma unroll
        for (int t = 0; t < 4; t++)
            cp16(&ws[0][(tid + t * 256) * 4], &g4[tid + t * 256]);
        cp_commit();
    }

    // ---- phase 0: LayerNorm for 8 instances (f = nn*2 + {c,s})
    if (active) {
        #pragma unroll
        for (int nn = 0; nn < 4; nn++) {
            size_t off = ((size_t)wg * 4 + nn) * HID + lane * 4;
            float4 c4 = *(const float4*)&g_hc[off];
            float4 s4 = *(const float4*)&g_hs[off];
            ln_store4(c4, lane, lns, lnb, &hnf[(nn * 2 + 0) * 128]);
            ln_store4(s4, lane, lns, lnb, &hnf[(nn * 2 + 1) * 128]);
        }
    }
    __syncwarp();

    // ---- GEMM1: g[f][j] = sum_i hn[f][i]*W1[i][j] + b1[j]
    //      lane owns j in {lane*4..+4} and {128+lane*4..+4}
    u64 a1[8][4];
    {
        ulonglong2 bA = *(const ulonglong2*)&b1[lane * 4];
        ulonglong2 bB = *(const ulonglong2*)&b1[128 + lane * 4];
        #pragma unroll
        for (int f = 0; f < 8; f++) {
            a1[f][0] = bA.x; a1[f][1] = bA.y; a1[f][2] = bB.x; a1[f][3] = bB.y;
        }
    }
    #pragma unroll 1
    for (int c = 0; c < 8; c++) {
        // stage next chunk while computing this one
        if (c < 7) {
            const float4* g4 = (const float4*)(W1 + (size_t)(c + 1) * 16 * 256);
            #pragma unroll
            for (int t = 0; t < 4; t++)
                cp16(&ws[(c + 1) & 1][(tid + t * 256) * 4], &g4[tid + t * 256]);
            cp_commit();
            asm volatile("cp.async.wait_group 1;\n" ::: "memory");
        } else {
            asm volatile("cp.async.wait_group 0;\n" ::: "memory");
        }
        __syncthreads();

        const float* wsb = ws[c & 1];
        #pragma unroll 1
        for (int ii = 0; ii < 16; ii += 2) {
            ulonglong2 wA0 = *(const ulonglong2*)&wsb[ii * 256 + lane * 4];
            ulonglong2 wB0 = *(const ulonglong2*)&wsb[ii * 256 + 128 + lane * 4];
            ulonglong2 wA1 = *(const ulonglong2*)&wsb[(ii + 1) * 256 + lane * 4];
            ulonglong2 wB1 = *(const ulonglong2*)&wsb[(ii + 1) * 256 + 128 + lane * 4];
            const int i = c * 16 + ii;

            #pragma unroll
            for (int f = 0; f < 8; f++) {
                float2 hv = *(const float2*)&hnf[f * 128 + i];
                u64 p0 = pack2(hv.x, hv.x);
                u64 p1 = pack2(hv.y, hv.y);
                a1[f][0] = fma2(p0, wA0.x, a1[f][0]);
                a1[f][1] = fma2(p0, wA0.y, a1[f][1]);
                a1[f][2] = fma2(p0, wB0.x, a1[f][2]);
                a1[f][3] = fma2(p0, wB0.y, a1[f][3]);
                a1[f][0] = fma2(p1, wA1.x, a1[f][0]);
                a1[f][1] = fma2(p1, wA1.y, a1[f][1]);
                a1[f][2] = fma2(p1, wB1.x, a1[f][2]);
                a1[f][3] = fma2(p1, wB1.y, a1[f][3]);
            }
        }
        __syncthreads();
    }

    // ---- kick off stage of W2 chunk 0 (32 rows x 128 = 16 KB)
    {
        const float4* g4 = (const float4*)W2;
        #pragma unroll
        for (int t = 0; t < 4; t++)
            cp16(&ws[0][(tid + t * 256) * 4], &g4[tid + t * 256]);
        cp_commit();
    }

    // ---- GELU, stage g to smem (logical cols lane*4 and 128+lane*4)
    #pragma unroll
    for (int f = 0; f < 8; f++) {
        float2 v0 = unpack2(a1[f][0]);
        float2 v1 = unpack2(a1[f][1]);
        float2 v2 = unpack2(a1[f][2]);
        float2 v3 = unpack2(a1[f][3]);
        *(float4*)&gb[f * 256 + lane * 4] =
            make_float4(gelu_exact(v0.x), gelu_exact(v0.y),
                        gelu_exact(v1.x), gelu_exact(v1.y));
        *(float4*)&gb[f * 256 + 128 + lane * 4] =
            make_float4(gelu_exact(v2.x), gelu_exact(v2.y),
                        gelu_exact(v3.x), gelu_exact(v3.y));
    }
    __syncwarp();

    // ---- GEMM2: r[f][d] = sum_j g[f][j]*W2[j][d] + b2[d], d = lane*4..+4
    u64 a2[8][2];
    {
        ulonglong2 bb = *(const ulonglong2*)&b2[lane * 4];
        #pragma unroll
        for (int f = 0; f < 8; f++) { a2[f][0] = bb.x; a2[f][1] = bb.y; }
    }
    #pragma unroll 1
    for (int c = 0; c < 8; c++) {
        if (c < 7) {
            const float4* g4 = (const float4*)(W2 + (size_t)(c + 1) * 32 * 128);
            #pragma unroll
            for (int t = 0; t < 4; t++)
                cp16(&ws[(c + 1) & 1][(tid + t * 256) * 4], &g4[tid + t * 256]);
            cp_commit();
            asm volatile("cp.async.wait_group 1;\n" ::: "memory");
        } else {
            asm volatile("cp.async.wait_group 0;\n" ::: "memory");
        }
        __syncthreads();

        const float* wsb = ws[c & 1];
        #pragma unroll 1
        for (int jj = 0; jj < 32; jj += 4) {
            ulonglong2 w0  = *(const ulonglong2*)&wsb[(jj + 0) * 128 + lane * 4];
            ulonglong2 w1  = *(const ulonglong2*)&wsb[(jj + 1) * 128 + lane * 4];
            ulonglong2 w2v = *(const ulonglong2*)&wsb[(jj + 2) * 128 + lane * 4];
            ulonglong2 w3v = *(const ulonglong2*)&wsb[(jj + 3) * 128 + lane * 4];
            const int j = c * 32 + jj;

            #pragma unroll
            for (int f = 0; f < 8; f++) {
                float4 gj = *(const float4*)&gb[f * 256 + j];
                u64 p0 = pack2(gj.x, gj.x);
                u64 p1 = pack2(gj.y, gj.y);
                u64 p2 = pack2(gj.z, gj.z);
                u64 p3 = pack2(gj.w, gj.w);
                a2[f][0] = fma2(p0, w0.x, a2[f][0]);
                a2[f][1] = fma2(p0, w0.y, a2[f][1]);
                a2[f][0] = fma2(p1, w1.x, a2[f][0]);
                a2[f][1] = fma2(p1, w1.y, a2[f][1]);
                a2[f][0] = fma2(p2, w2v.x, a2[f][0]);
                a2[f][1] = fma2(p2, w2v.y, a2[f][1]);
                a2[f][0] = fma2(p3, w3v.x, a2[f][0]);
                a2[f][1] = fma2(p3, w3v.y, a2[f][1]);
            }
        }
        __syncthreads();
    }

    if (!active) return;

    // ---- epilogue: residual (reload h, L2-hot), write xs/cs/ss
    const size_t S = (size_t)TN * HID;
    #pragma unroll
    for (int nn = 0; nn < 4; nn++) {
        size_t off = ((size_t)wg * 4 + nn) * HID + lane * 4;
        float4 c4 = *(const float4*)&g_hc[off];
        float4 s4 = *(const float4*)&g_hs[off];

        float2 c01 = unpack2(a2[nn * 2][0]);
        float2 c23 = unpack2(a2[nn * 2][1]);
        float2 s01 = unpack2(a2[nn * 2 + 1][0]);
        float2 s23 = unpack2(a2[nn * 2 + 1][1]);
        float oc[4] = { c4.x + c01.x, c4.y + c01.y, c4.z + c23.x, c4.w + c23.y };
        float os[4] = { s4.x + s01.x, s4.y + s01.y, s4.z + s23.x, s4.w + s23.y };

        *(float4*)&out[off]         = make_float4(oc[0]+os[0], oc[1]+os[1],
                                                  oc[2]+os[2], oc[3]+os[3]);
        *(float4*)&out[S + off]     = make_float4(oc[0], oc[1], oc[2], oc[3]);
        *(float4*)&out[2*S + off]   = make_float4(os[0], os[1], os[2], os[3]);
    }
}

// ---------------------------------------------------------------------------
// Launch
// ---------------------------------------------------------------------------
extern "C" void kernel_launch(void* const* d_in, const int* in_sizes, int n_in,
                              void* d_out, int out_size) {
    const float* x    = (const float*)d_in[0];
    const int*   ei   = (const int*)  d_in[1];
    const float* Wq   = (const float*)d_in[2];
    const float* bq   = (const float*)d_in[3];
    const float* Wk   = (const float*)d_in[4];
    const float* bk   = (const float*)d_in[5];
    const float* Wv   = (const float*)d_in[6];
    const float* bv   = (const float*)d_in[7];
    const float* ln_s = (const float*)d_in[8];
    const float* ln_b = (const float*)d_in[9];
    const float* W1   = (const float*)d_in[10];
    const float* b1   = (const float*)d_in[11];
    const float* W2   = (const float*)d_in[12];
    const float* b2   = (const float*)d_in[13];
    float* out = (float*)d_out;

    // CSR build (depends only on edge_index)
    zero_cnt_kernel<<<(T_WIN * N_NODES + 255) / 256, 256>>>();
    count_kernel<<<(T_WIN * E_PER_T + 255) / 256, 256>>>(ei);
    scan_kernel<<<T_WIN, 1024>>>();
    fill_kernel<<<(T_WIN * E_PER_T + 255) / 256, 256>>>(ei);

    // QKV projections
    qkv_kernel<<<dim3((M_ROWS + 63) / 64, 3), 256>>>(x, Wq, bq, Wk, bk, Wv, bv);

    // Gather-aggregate (2-edge ILP)
    agg_kernel<<<dim3((N_NODES * 32 + 255) / 256, T_WIN), 256>>>(x);

    // Dual FFN (8 warps x 4 nodes per block)
    ffn_kernel<<<(TN / 4 + 7) / 8, 256>>>(ln_s, ln_b, W1, b1, W2, b2, out);
}

// round 11
// speedup vs baseline: 1.2017x; 1.1018x over previous
#include <cuda_runtime.h>
#include <math.h>

// ---------------------------------------------------------------------------
// Problem constants
// ---------------------------------------------------------------------------
#define N_NODES 50000
#define T_WIN   3
#define E_PER_T 100000
#define HID     128
#define NH      8
#define DK      16
#define M_ROWS  (T_WIN * N_NODES)          // 150000 rows
#define TN      (T_WIN * N_NODES)

// ---------------------------------------------------------------------------
// Device scratch
// ---------------------------------------------------------------------------
__device__ float g_q[(size_t)M_ROWS * HID];
__device__ float g_k[(size_t)M_ROWS * HID];
__device__ float g_v[(size_t)M_ROWS * HID];
__device__ float g_hc[(size_t)TN * HID];        // normalized causal + residual x
__device__ float g_hs[(size_t)TN * HID];        // normalized spurious
__device__ int   g_cnt[T_WIN * N_NODES];        // histogram, then CSR cursor
__device__ int   g_off[T_WIN * (N_NODES + 1)];  // CSR offsets
__device__ int   g_csr[T_WIN * E_PER_T];        // src node ids, grouped by target

// ---------------------------------------------------------------------------
// Packed fp32x2 helpers (B300 FFMA2 path)
// ---------------------------------------------------------------------------
typedef unsigned long long u64;

__device__ __forceinline__ u64 fma2(u64 a, u64 b, u64 c) {
    u64 d;
    asm("fma.rn.f32x2 %0, %1, %2, %3;" : "=l"(d) : "l"(a), "l"(b), "l"(c));
    return d;
}
__device__ __forceinline__ u64 pack2(float lo, float hi) {
    u64 r;
    asm("mov.b64 %0, {%1, %2};" : "=l"(r) : "f"(lo), "f"(hi));
    return r;
}
__device__ __forceinline__ float2 unpack2(u64 v) {
    float2 f;
    asm("mov.b64 {%0, %1}, %2;" : "=f"(f.x), "=f"(f.y) : "l"(v));
    return f;
}

// cp.async 16B
__device__ __forceinline__ void cp16(void* sdst, const void* gsrc) {
    unsigned sa = (unsigned)__cvta_generic_to_shared(sdst);
    asm volatile("cp.async.ca.shared.global [%0], [%1], 16;\n"
                 :: "r"(sa), "l"(gsrc) : "memory");
}
__device__ __forceinline__ void cp_commit() {
    asm volatile("cp.async.commit_group;\n" ::: "memory");
}

// ---------------------------------------------------------------------------
// CSR build: zero -> count -> scan -> fill
// ---------------------------------------------------------------------------
__global__ void zero_cnt_kernel() {
    int i = blockIdx.x * blockDim.x + threadIdx.x;
    if (i < T_WIN * N_NODES) g_cnt[i] = 0;
}

__global__ void count_kernel(const int* __restrict__ ei) {
    int g = blockIdx.x * blockDim.x + threadIdx.x;
    if (g >= T_WIN * E_PER_T) return;
    int t   = g / E_PER_T;
    int idx = g - t * E_PER_T;
    int tar = ei[(size_t)t * 2 * E_PER_T + E_PER_T + idx];
    atomicAdd(&g_cnt[t * N_NODES + tar], 1);
}

// One block (1024 thr) per t: exclusive scan of 50000 counts.
__global__ void __launch_bounds__(1024) scan_kernel() {
    const int t    = blockIdx.x;
    const int tid  = threadIdx.x;
    const int lane = tid & 31;
    const int wid  = tid >> 5;
    __shared__ int wsum[32];
    __shared__ int sbase;
    if (tid == 0) sbase = 0;
    __syncthreads();

    for (int c0 = 0; c0 < N_NODES; c0 += 1024) {
        int i = c0 + tid;
        int v = (i < N_NODES) ? g_cnt[t * N_NODES + i] : 0;
        int incl = v;
        #pragma unroll
        for (int o = 1; o < 32; o <<= 1) {
            int u = __shfl_up_sync(0xFFFFFFFFu, incl, o);
            if (lane >= o) incl += u;
        }
        if (lane == 31) wsum[wid] = incl;
        __syncthreads();
        if (wid == 0) {
            int wv = wsum[lane];
            #pragma unroll
            for (int o = 1; o < 32; o <<= 1) {
                int u = __shfl_up_sync(0xFFFFFFFFu, wv, o);
                if (lane >= o) wv += u;
            }
            wsum[lane] = wv;
        }
        __syncthreads();
        int excl = (wid > 0 ? wsum[wid - 1] : 0) + sbase + incl - v;
        if (i < N_NODES) {
            g_off[t * (N_NODES + 1) + i] = excl;
            g_cnt[t * N_NODES + i]       = excl;   // becomes fill cursor
        }
        __syncthreads();
        if (tid == 0) sbase += wsum[31];
        __syncthreads();
    }
    if (tid == 0) g_off[t * (N_NODES + 1) + N_NODES] = sbase;
}

__global__ void fill_kernel(const int* __restrict__ ei) {
    int g = blockIdx.x * blockDim.x + threadIdx.x;
    if (g >= T_WIN * E_PER_T) return;
    int t   = g / E_PER_T;
    int idx = g - t * E_PER_T;
    int src = ei[(size_t)t * 2 * E_PER_T + idx];
    int tar = ei[(size_t)t * 2 * E_PER_T + E_PER_T + idx];
    int pos = atomicAdd(&g_cnt[t * N_NODES + tar], 1);
    g_csr[(size_t)t * E_PER_T + pos] = src;
}

// ---------------------------------------------------------------------------
// K_qkv v2: BM=128 (8 rows/thread), BN=128, BK=32. Packed f32x2 math.
// Per-k: 2 W LDS.128 + 8 X LDS.32 + 8 MOV + 32 fma2 (50 issues / 64 fma-cyc).
// ---------------------------------------------------------------------------
__global__ void __launch_bounds__(256) qkv_kernel(
        const float* __restrict__ x,
        const float* __restrict__ Wq, const float* __restrict__ bq,
        const float* __restrict__ Wk, const float* __restrict__ bk,
        const float* __restrict__ Wv, const float* __restrict__ bv) {
    const float* W; const float* b; float* out;
    if (blockIdx.y == 0)      { W = Wq; b = bq; out = g_q; }
    else if (blockIdx.y == 1) { W = Wk; b = bk; out = g_k; }
    else                      { W = Wv; b = bv; out = g_v; }

    __shared__ float Xs[128][33];
    __shared__ float Ws[32][128];

    const int tid  = threadIdx.x;
    const int m0   = blockIdx.x * 128;
    const int ty   = tid >> 4;            // 0..15
    const int tx   = tid & 15;            // 0..15
    const int row0 = ty * 8;
    const int col0 = tx * 8;

    u64 acc[8][4];
    #pragma unroll
    for (int i = 0; i < 8; i++)
        #pragma unroll
        for (int j = 0; j < 4; j++) acc[i][j] = 0ull;

    for (int kc = 0; kc < 128; kc += 32) {
        // stage X tile 128x32 (1024 float4 over 256 threads)
        #pragma unroll
        for (int l = 0; l < 4; l++) {
            int f4 = tid + l * 256;       // 0..1023
            int r  = f4 >> 3;             // 0..127
            int c4 = f4 & 7;
            int grow = m0 + r;
            float4 val = make_float4(0.f, 0.f, 0.f, 0.f);
            if (grow < M_ROWS)
                val = *(const float4*)&x[(size_t)grow * HID + kc + c4 * 4];
            Xs[r][c4 * 4 + 0] = val.x;
            Xs[r][c4 * 4 + 1] = val.y;
            Xs[r][c4 * 4 + 2] = val.z;
            Xs[r][c4 * 4 + 3] = val.w;
        }
        // stage W tile 32x128 (1024 float4)
        #pragma unroll
        for (int l = 0; l < 4; l++) {
            int f4 = tid + l * 256;
            int r  = f4 >> 5;
            int c4 = f4 & 31;
            *(float4*)&Ws[r][c4 * 4] =
                *(const float4*)&W[(size_t)(kc + r) * HID + c4 * 4];
        }
        __syncthreads();

        #pragma unroll
        for (int k = 0; k < 32; k++) {
            ulonglong2 wb0 = *(const ulonglong2*)&Ws[k][col0];
            ulonglong2 wb1 = *(const ulonglong2*)&Ws[k][col0 + 4];
            #pragma unroll
            for (int i = 0; i < 8; i++) {
                u64 ap = pack2(Xs[row0 + i][k], Xs[row0 + i][k]);
                acc[i][0] = fma2(ap, wb0.x, acc[i][0]);
                acc[i][1] = fma2(ap, wb0.y, acc[i][1]);
                acc[i][2] = fma2(ap, wb1.x, acc[i][2]);
                acc[i][3] = fma2(ap, wb1.y, acc[i][3]);
            }
        }
        __syncthreads();
    }

    #pragma unroll
    for (int i = 0; i < 8; i++) {
        int grow = m0 + row0 + i;
        if (grow < M_ROWS) {
            float o[8];
            #pragma unroll
            for (int j = 0; j < 4; j++) {
                float2 v = unpack2(acc[i][j]);
                o[j * 2]     = v.x + b[col0 + j * 2];
                o[j * 2 + 1] = v.y + b[col0 + j * 2 + 1];
            }
            *(float4*)&out[(size_t)grow * HID + col0]     = make_float4(o[0], o[1], o[2], o[3]);
            *(float4*)&out[(size_t)grow * HID + col0 + 4] = make_float4(o[4], o[5], o[6], o[7]);
        }
    }
}

// ---------------------------------------------------------------------------
// K_agg v3: warp per NODE. k/v for each (t_src, edge) loaded ONCE and fed to
// all t_tar >= t_src (gather traffic halved vs per-(t_tar,node) version).
// The 1-3 independent dot->shfl->exp chains per edge provide the ILP that
// edge pairing couldn't (mean degree is only 2).
// ---------------------------------------------------------------------------
__global__ void __launch_bounds__(256) agg_kernel(const float* __restrict__ x) {
    const int warp = (blockIdx.x * blockDim.x + threadIdx.x) >> 5;
    const int lane = threadIdx.x & 31;
    if (warp >= N_NODES) return;
    const int n = warp;

    float4 q4[T_WIN];
    #pragma unroll
    for (int tt = 0; tt < T_WIN; tt++)
        q4[tt] = *(const float4*)&g_q[((size_t)tt * N_NODES + n) * HID + lane * 4];

    float ac[T_WIN][4], as[T_WIN][4], sc[T_WIN], ss[T_WIN];
    #pragma unroll
    for (int tt = 0; tt < T_WIN; tt++) {
        ac[tt][0] = ac[tt][1] = ac[tt][2] = ac[tt][3] = 0.f;
        as[tt][0] = as[tt][1] = as[tt][2] = as[tt][3] = 0.f;
        sc[tt] = 0.f; ss[tt] = 0.f;
    }

    #pragma unroll
    for (int ts = 0; ts < T_WIN; ts++) {
        const int s0 = g_off[ts * (N_NODES + 1) + n];
        const int s1 = g_off[ts * (N_NODES + 1) + n + 1];
        const int* csr = g_csr + (size_t)ts * E_PER_T;
        const float* kb = g_k + (size_t)ts * N_NODES * HID;
        const float* vb = g_v + (size_t)ts * N_NODES * HID;

        for (int e = s0; e < s1; e++) {
            int src = csr[e];
            size_t so = (size_t)src * HID + lane * 4;
            float4 k4 = *(const float4*)&kb[so];
            float4 v4 = *(const float4*)&vb[so];

            // independent chains per t_tar >= ts
            float d[T_WIN];
            #pragma unroll
            for (int tt = 0; tt < T_WIN; tt++) {
                if (tt < ts) continue;
                d[tt] = q4[tt].x * k4.x + q4[tt].y * k4.y
                      + q4[tt].z * k4.z + q4[tt].w * k4.w;
            }
            #pragma unroll
            for (int tt = 0; tt < T_WIN; tt++) {
                if (tt < ts) continue;
                d[tt] += __shfl_xor_sync(0xFFFFFFFFu, d[tt], 1);
            }
            #pragma unroll
            for (int tt = 0; tt < T_WIN; tt++) {
                if (tt < ts) continue;
                d[tt] += __shfl_xor_sync(0xFFFFFFFFu, d[tt], 2);
            }
            #pragma unroll
            for (int tt = 0; tt < T_WIN; tt++) {
                if (tt < ts) continue;
                float a  = d[tt] * 0.25f;     // 1/sqrt(16)
                float ec = expf(a);
                float es = expf(-a);
                sc[tt] += ec;  ss[tt] += es;
                ac[tt][0] = fmaf(ec, v4.x, ac[tt][0]);
                ac[tt][1] = fmaf(ec, v4.y, ac[tt][1]);
                ac[tt][2] = fmaf(ec, v4.z, ac[tt][2]);
                ac[tt][3] = fmaf(ec, v4.w, ac[tt][3]);
                as[tt][0] = fmaf(es, v4.x, as[tt][0]);
                as[tt][1] = fmaf(es, v4.y, as[tt][1]);
                as[tt][2] = fmaf(es, v4.z, as[tt][2]);
                as[tt][3] = fmaf(es, v4.w, as[tt][3]);
            }
        }
    }

    #pragma unroll
    for (int tt = 0; tt < T_WIN; tt++) {
        size_t rowoff = ((size_t)tt * N_NODES + n) * HID + lane * 4;
        const float ic = 1.0f / (sc[tt] + 1e-16f);
        const float is = 1.0f / (ss[tt] + 1e-16f);
        const float4 xv = *(const float4*)&x[rowoff];
        *(float4*)&g_hc[rowoff] = make_float4(
            fmaf(ac[tt][0], ic, xv.x), fmaf(ac[tt][1], ic, xv.y),
            fmaf(ac[tt][2], ic, xv.z), fmaf(ac[tt][3], ic, xv.w));
        *(float4*)&g_hs[rowoff] = make_float4(
            as[tt][0] * is, as[tt][1] * is, as[tt][2] * is, as[tt][3] * is);
    }
}

// ---------------------------------------------------------------------------
// K_ffn (round-6 v5, the empirical best): warp = 4 nodes (8 instances),
// f32x2 packed math, 2 blocks/SM. W1/W2 staged block-cooperatively via
// cp.async double buffer. Lane owns j-cols {lane*4..+4, 128+lane*4..+4}.
// ---------------------------------------------------------------------------
__device__ __forceinline__ float gelu_exact(float v) {
    return 0.5f * v * (1.0f + erff(v * 0.70710678118654752f));
}

__device__ __forceinline__ void ln_store4(float4 h4, int lane,
                                          float4 lns, float4 lnb,
                                          float* __restrict__ dst) {
    float s1 = h4.x + h4.y + h4.z + h4.w;
    float s2 = h4.x*h4.x + h4.y*h4.y + h4.z*h4.z + h4.w*h4.w;
    #pragma unroll
    for (int o = 16; o > 0; o >>= 1) {
        s1 += __shfl_xor_sync(0xFFFFFFFFu, s1, o);
        s2 += __shfl_xor_sync(0xFFFFFFFFu, s2, o);
    }
    float mu   = s1 * (1.0f / 128.0f);
    float var  = s2 * (1.0f / 128.0f) - mu * mu;
    float rstd = rsqrtf(var + 1e-5f);

    *(float4*)&dst[lane * 4] = make_float4(
        (h4.x - mu) * rstd * lns.x + lnb.x,
        (h4.y - mu) * rstd * lns.y + lnb.y,
        (h4.z - mu) * rstd * lns.z + lnb.z,
        (h4.w - mu) * rstd * lns.w + lnb.w);
}

__global__ void __launch_bounds__(256, 2) ffn_kernel(
        const float* __restrict__ ln_s, const float* __restrict__ ln_b,
        const float* __restrict__ W1, const float* __restrict__ b1,
        const float* __restrict__ W2, const float* __restrict__ b2,
        float* __restrict__ out) {
    __shared__ float sbuf[8][2048];                    // 64 KB per-warp hn/g
    __shared__ __align__(16) float ws[2][4096];        // 32 KB W stage (db)

    const int tid  = threadIdx.x;
    const int wib  = tid >> 5;
    const int lane = tid & 31;
    const int wg   = blockIdx.x * 8 + wib;     // warp id over TN/4 = 37500
    const bool active = (wg < TN / 4);

    float* hnf = sbuf[wib];
    float* gb  = sbuf[wib];

    const float4 lns = active ? *(const float4*)&ln_s[lane * 4] : make_float4(0,0,0,0);
    const float4 lnb = active ? *(const float4*)&ln_b[lane * 4] : make_float4(0,0,0,0);

    // ---- kick off stage of W1 chunk 0 (16 rows x 256 = 16 KB)
    {
        const float4* g4 = (const float4*)W1;
        #pragma unroll
        for (int t = 0; t < 4; t++)
            cp16(&ws[0][(tid + t * 256) * 4], &g4[tid + t * 256]);
        cp_commit();
    }

    // ---- phase 0: LayerNorm for 8 instances (f = nn*2 + {c,s})
    if (active) {
        #pragma unroll
        for (int nn = 0; nn < 4; nn++) {
            size_t off = ((size_t)wg * 4 + nn) * HID + lane * 4;
            float4 c4 = *(const float4*)&g_hc[off];
            float4 s4 = *(const float4*)&g_hs[off];
            ln_store4(c4, lane, lns, lnb, &hnf[(nn * 2 + 0) * 128]);
            ln_store4(s4, lane, lns, lnb, &hnf[(nn * 2 + 1) * 128]);
        }
    }
    __syncwarp();

    // ---- GEMM1: g[f][j] = sum_i hn[f][i]*W1[i][j] + b1[j]
    //      lane owns j in {lane*4..+4} and {128+lane*4..+4}
    u64 a1[8][4];
    {
        ulonglong2 bA = *(const ulonglong2*)&b1[lane * 4];
        ulonglong2 bB = *(const ulonglong2*)&b1[128 + lane * 4];
        #pragma unroll
        for (int f = 0; f < 8; f++) {
            a1[f][0] = bA.x; a1[f][1] = bA.y; a1[f][2] = bB.x; a1[f][3] = bB.y;
        }
    }
    #pragma unroll 1
    for (int c = 0; c < 8; c++) {
        // stage next chunk while computing this one
        if (c < 7) {
            const float4* g4 = (const float4*)(W1 + (size_t)(c + 1) * 16 * 256);
            #pragma unroll
            for (int t = 0; t < 4; t++)
                cp16(&ws[(c + 1) & 1][(tid + t * 256) * 4], &g4[tid + t * 256]);
            cp_commit();
            asm volatile("cp.async.wait_group 1;\n" ::: "memory");
        } else {
            asm volatile("cp.async.wait_group 0;\n" ::: "memory");
        }
        __syncthreads();

        const float* wsb = ws[c & 1];
        #pragma unroll 1
        for (int ii = 0; ii < 16; ii += 2) {
            ulonglong2 wA0 = *(const ulonglong2*)&wsb[ii * 256 + lane * 4];
            ulonglong2 wB0 = *(const ulonglong2*)&wsb[ii * 256 + 128 + lane * 4];
            ulonglong2 wA1 = *(const ulonglong2*)&wsb[(ii + 1) * 256 + lane * 4];
            ulonglong2 wB1 = *(const ulonglong2*)&wsb[(ii + 1) * 256 + 128 + lane * 4];
            const int i = c * 16 + ii;

            #pragma unroll
            for (int f = 0; f < 8; f++) {
                float2 hv = *(const float2*)&hnf[f * 128 + i];
                u64 p0 = pack2(hv.x, hv.x);
                u64 p1 = pack2(hv.y, hv.y);
                a1[f][0] = fma2(p0, wA0.x, a1[f][0]);
                a1[f][1] = fma2(p0, wA0.y, a1[f][1]);
                a1[f][2] = fma2(p0, wB0.x, a1[f][2]);
                a1[f][3] = fma2(p0, wB0.y, a1[f][3]);
                a1[f][0] = fma2(p1, wA1.x, a1[f][0]);
                a1[f][1] = fma2(p1, wA1.y, a1[f][1]);
                a1[f][2] = fma2(p1, wB1.x, a1[f][2]);
                a1[f][3] = fma2(p1, wB1.y, a1[f][3]);
            }
        }
        __syncthreads();
    }

    // ---- kick off stage of W2 chunk 0 (32 rows x 128 = 16 KB)
    {
        const float4* g4 = (const float4*)W2;
        #pragma unroll
        for (int t = 0; t < 4; t++)
            cp16(&ws[0][(tid + t * 256) * 4], &g4[tid + t * 256]);
        cp_commit();
    }

    // ---- GELU, stage g to smem (logical cols lane*4 and 128+lane*4)
    #pragma unroll
    for (int f = 0; f < 8; f++) {
        float2 v0 = unpack2(a1[f][0]);
        float2 v1 = unpack2(a1[f][1]);
        float2 v2 = unpack2(a1[f][2]);
        float2 v3 = unpack2(a1[f][3]);
        *(float4*)&gb[f * 256 + lane * 4] =
            make_float4(gelu_exact(v0.x), gelu_exact(v0.y),
                        gelu_exact(v1.x), gelu_exact(v1.y));
        *(float4*)&gb[f * 256 + 128 + lane * 4] =
            make_float4(gelu_exact(v2.x), gelu_exact(v2.y),
                        gelu_exact(v3.x), gelu_exact(v3.y));
    }
    __syncwarp();

    // ---- GEMM2: r[f][d] = sum_j g[f][j]*W2[j][d] + b2[d], d = lane*4..+4
    u64 a2[8][2];
    {
        ulonglong2 bb = *(const ulonglong2*)&b2[lane * 4];
        #pragma unroll
        for (int f = 0; f < 8; f++) { a2[f][0] = bb.x; a2[f][1] = bb.y; }
    }
    #pragma unroll 1
    for (int c = 0; c < 8; c++) {
        if (c < 7) {
            const float4* g4 = (const float4*)(W2 + (size_t)(c + 1) * 32 * 128);
            #pragma unroll
            for (int t = 0; t < 4; t++)
                cp16(&ws[(c + 1) & 1][(tid + t * 256) * 4], &g4[tid + t * 256]);
            cp_commit();
            asm volatile("cp.async.wait_group 1;\n" ::: "memory");
        } else {
            asm volatile("cp.async.wait_group 0;\n" ::: "memory");
        }
        __syncthreads();

        const float* wsb = ws[c & 1];
        #pragma unroll 1
        for (int jj = 0; jj < 32; jj += 4) {
            ulonglong2 w0  = *(const ulonglong2*)&wsb[(jj + 0) * 128 + lane * 4];
            ulonglong2 w1  = *(const ulonglong2*)&wsb[(jj + 1) * 128 + lane * 4];
            ulonglong2 w2v = *(const ulonglong2*)&wsb[(jj + 2) * 128 + lane * 4];
            ulonglong2 w3v = *(const ulonglong2*)&wsb[(jj + 3) * 128 + lane * 4];
            const int j = c * 32 + jj;

            #pragma unroll
            for (int f = 0; f < 8; f++) {
                float4 gj = *(const float4*)&gb[f * 256 + j];
                u64 p0 = pack2(gj.x, gj.x);
                u64 p1 = pack2(gj.y, gj.y);
                u64 p2 = pack2(gj.z, gj.z);
                u64 p3 = pack2(gj.w, gj.w);
                a2[f][0] = fma2(p0, w0.x, a2[f][0]);
                a2[f][1] = fma2(p0, w0.y, a2[f][1]);
                a2[f][0] = fma2(p1, w1.x, a2[f][0]);
                a2[f][1] = fma2(p1, w1.y, a2[f][1]);
                a2[f][0] = fma2(p2, w2v.x, a2[f][0]);
                a2[f][1] = fma2(p2, w2v.y, a2[f][1]);
                a2[f][0] = fma2(p3, w3v.x, a2[f][0]);
                a2[f][1] = fma2(p3, w3v.y, a2[f][1]);
            }
        }
        __syncthreads();
    }

    if (!active) return;

    // ---- epilogue: residual (reload h, L2-hot), write xs/cs/ss
    const size_t S = (size_t)TN * HID;
    #pragma unroll
    for (int nn = 0; nn < 4; nn++) {
        size_t off = ((size_t)wg * 4 + nn) * HID + lane * 4;
        float4 c4 = *(const float4*)&g_hc[off];
        float4 s4 = *(const float4*)&g_hs[off];

        float2 c01 = unpack2(a2[nn * 2][0]);
        float2 c23 = unpack2(a2[nn * 2][1]);
        float2 s01 = unpack2(a2[nn * 2 + 1][0]);
        float2 s23 = unpack2(a2[nn * 2 + 1][1]);
        float oc[4] = { c4.x + c01.x, c4.y + c01.y, c4.z + c23.x, c4.w + c23.y };
        float os[4] = { s4.x + s01.x, s4.y + s01.y, s4.z + s23.x, s4.w + s23.y };

        *(float4*)&out[off]         = make_float4(oc[0]+os[0], oc[1]+os[1],
                                                  oc[2]+os[2], oc[3]+os[3]);
        *(float4*)&out[S + off]     = make_float4(oc[0], oc[1], oc[2], oc[3]);
        *(float4*)&out[2*S + off]   = make_float4(os[0], os[1], os[2], os[3]);
    }
}

// ---------------------------------------------------------------------------
// Launch
// ---------------------------------------------------------------------------
extern "C" void kernel_launch(void* const* d_in, const int* in_sizes, int n_in,
                              void* d_out, int out_size) {
    const float* x    = (const float*)d_in[0];
    const int*   ei   = (const int*)  d_in[1];
    const float* Wq   = (const float*)d_in[2];
    const float* bq   = (const float*)d_in[3];
    const float* Wk   = (const float*)d_in[4];
    const float* bk   = (const float*)d_in[5];
    const float* Wv   = (const float*)d_in[6];
    const float* bv   = (const float*)d_in[7];
    const float* ln_s = (const float*)d_in[8];
    const float* ln_b = (const float*)d_in[9];
    const float* W1   = (const float*)d_in[10];
    const float* b1   = (const float*)d_in[11];
    const float* W2   = (const float*)d_in[12];
    const float* b2   = (const float*)d_in[13];
    float* out = (float*)d_out;

    // CSR build (depends only on edge_index)
    zero_cnt_kernel<<<(T_WIN * N_NODES + 255) / 256, 256>>>();
    count_kernel<<<(T_WIN * E_PER_T + 255) / 256, 256>>>(ei);
    scan_kernel<<<T_WIN, 1024>>>();
    fill_kernel<<<(T_WIN * E_PER_T + 255) / 256, 256>>>(ei);

    // QKV projections (BM=128)
    qkv_kernel<<<dim3((M_ROWS + 127) / 128, 3), 256>>>(x, Wq, bq, Wk, bk, Wv, bv);

    // Gather-aggregate: warp per node, all t_tar at once
    agg_kernel<<<(N_NODES * 32 + 255) / 256, 256>>>(x);

    // Dual FFN (8 warps x 4 nodes per block)
    ffn_kernel<<<(TN / 4 + 7) / 8, 256>>>(ln_s, ln_b, W1, b1, W2, b2, out);
}